// round 3
// baseline (speedup 1.0000x reference)
#include <cuda_runtime.h>
#include <cuda_bf16.h>

// ---------------- problem constants ----------------
#define B_    2
#define T_    8192
#define D_    1024
#define H_    4
#define HD_   256
#define C_    64
#define N_    128
#define BH_   8

typedef unsigned long long ull;

// ---------------- f32x2 helpers (PTX-only on sm_103a) ----------------
__device__ __forceinline__ ull pk2(float a, float b) {
    ull r; asm("mov.b64 %0, {%1, %2};" : "=l"(r) : "f"(a), "f"(b)); return r;
}
__device__ __forceinline__ float2 upk2(ull v) {
    float2 f; asm("mov.b64 {%0, %1}, %2;" : "=f"(f.x), "=f"(f.y) : "l"(v)); return f;
}
__device__ __forceinline__ ull fma2(ull a, ull b, ull c) {
    ull d; asm("fma.rn.f32x2 %0, %1, %2, %3;" : "=l"(d) : "l"(a), "l"(b), "l"(c)); return d;
}
__device__ __forceinline__ ull add2(ull a, ull b) {
    ull d; asm("add.rn.f32x2 %0, %1, %2;" : "=l"(d) : "l"(a), "l"(b)); return d;
}
__device__ __forceinline__ ull mul2(ull a, ull b) {
    ull d; asm("mul.rn.f32x2 %0, %1, %2;" : "=l"(d) : "l"(a), "l"(b)); return d;
}
#define SGN2 0x8000000080000000ULL

// ---------------- device scratch (no allocation allowed) ----------------
__device__ float g_v[(size_t)B_ * T_ * D_];            // x @ Ww^T, (b*T+t, D) layout
__device__ float g_rk[(size_t)BH_ * T_ * HD_];         // normalized keys, (bh, t, d)
__device__ float g_vcorr[(size_t)BH_ * N_ * C_ * HD_]; // A @ v
__device__ float g_wkcorr[(size_t)BH_ * N_ * C_ * HD_];// A @ wk
__device__ float g_intra[(size_t)BH_ * N_ * C_ * C_];  // strict(rk wk^T * L)
__device__ float g_o[(size_t)B_ * T_ * D_];            // alpha * o, (b*T+t, D)
__device__ float g_gpow[H_][C_ + 1];                   // gamma^0..gamma^64
__device__ float g_alpha[H_];

// ---------------- setup ----------------
__global__ void setup_kernel(const float* __restrict__ decay,
                             const float* __restrict__ log_alpha) {
    int h = threadIdx.x;
    if (h < H_) {
        float g = 1.f / (1.f + expf(-decay[h]));
        g_alpha[h] = expf(log_alpha[h]);
        float p = 1.f;
        for (int i = 0; i <= C_; i++) { g_gpow[h][i] = p; p *= g; }
    }
}

// ---------------- rk: normalize per head, store (bh,t,d) ----------------
__global__ __launch_bounds__(256) void rk_kernel(const float* __restrict__ x) {
    int warp = threadIdx.x >> 5, lane = threadIdx.x & 31;
    int row = blockIdx.x * 8 + warp;            // (b*T+t)*H + h, total 65536
    int h  = row & (H_ - 1);
    int bt = row >> 2;
    const float* xp = x + (size_t)bt * D_ + h * HD_ + lane * 8;
    float4 v0 = *(const float4*)(xp);
    float4 v1 = *(const float4*)(xp + 4);
    float ss = v0.x*v0.x + v0.y*v0.y + v0.z*v0.z + v0.w*v0.w
             + v1.x*v1.x + v1.y*v1.y + v1.z*v1.z + v1.w*v1.w;
    #pragma unroll
    for (int o = 16; o; o >>= 1) ss += __shfl_xor_sync(0xffffffffu, ss, o);
    float inv = 1.f / fmaxf(sqrtf(ss), 1e-12f);
    int b = bt >> 13, t = bt & (T_ - 1);
    float* rp = g_rk + ((size_t)(b * H_ + h) * T_ + t) * HD_ + lane * 8;
    *(float4*)(rp)     = make_float4(v0.x*inv, v0.y*inv, v0.z*inv, v0.w*inv);
    *(float4*)(rp + 4) = make_float4(v1.x*inv, v1.y*inv, v1.z*inv, v1.w*inv);
}

// ---------------- SGEMM (TN): C[m,n] = (Cin?Cin[m,n]:0) + sum_k A[m,k]*W[n,k] ----------
// M=16384, N=1024, K=1024. 128x128 tile, 256 threads, 16x4 microtile, f32x2 FMAs.
__global__ __launch_bounds__(256) void sgemm_tn(const float* __restrict__ A,
                                                const float* __restrict__ W,
                                                const float* __restrict__ Cin,
                                                float* __restrict__ Cout) {
    __shared__ float As[8 * 132];
    __shared__ float Ws[8 * 132];
    const int tid = threadIdx.x;
    const int tx = tid & 31, ty = tid >> 5;           // 32 x 8
    const int bm = blockIdx.y * 128, bn = blockIdx.x * 128;
    const int r = tid >> 1, c4 = (tid & 1) * 4;
    const float* Abase = A + (size_t)(bm + r) * D_ + c4;
    const float* Wbase = W + (size_t)(bn + r) * D_ + c4;

    ull acc[8][4];
    #pragma unroll
    for (int p = 0; p < 8; p++)
        #pragma unroll
        for (int j = 0; j < 4; j++) acc[p][j] = 0ULL;

    float4 pa = *(const float4*)(Abase);
    float4 pw = *(const float4*)(Wbase);

    for (int k0 = 0; k0 < D_; k0 += 8) {
        __syncthreads();
        As[(c4+0)*132 + r] = pa.x; As[(c4+1)*132 + r] = pa.y;
        As[(c4+2)*132 + r] = pa.z; As[(c4+3)*132 + r] = pa.w;
        Ws[(c4+0)*132 + r] = pw.x; Ws[(c4+1)*132 + r] = pw.y;
        Ws[(c4+2)*132 + r] = pw.z; Ws[(c4+3)*132 + r] = pw.w;
        __syncthreads();
        if (k0 + 8 < D_) {
            pa = *(const float4*)(Abase + k0 + 8);
            pw = *(const float4*)(Wbase + k0 + 8);
        }
        #pragma unroll
        for (int kk = 0; kk < 8; kk++) {
            const ulonglong2* ap = (const ulonglong2*)(As + kk*132 + ty*16);
            ulonglong2 a01 = ap[0], a23 = ap[1], a45 = ap[2], a67 = ap[3];
            ull ar[8] = {a01.x, a01.y, a23.x, a23.y, a45.x, a45.y, a67.x, a67.y};
            float4 b4 = *(const float4*)(Ws + kk*132 + tx*4);
            ull b2[4] = {pk2(b4.x,b4.x), pk2(b4.y,b4.y), pk2(b4.z,b4.z), pk2(b4.w,b4.w)};
            #pragma unroll
            for (int p = 0; p < 8; p++)
                #pragma unroll
                for (int j = 0; j < 4; j++)
                    acc[p][j] = fma2(ar[p], b2[j], acc[p][j]);
        }
    }

    const int colb = bn + tx * 4;
    #pragma unroll
    for (int p = 0; p < 8; p++) {
        float2 f0 = upk2(acc[p][0]), f1 = upk2(acc[p][1]);
        float2 f2 = upk2(acc[p][2]), f3 = upk2(acc[p][3]);
        int row0 = bm + ty*16 + 2*p;
        float4 lo = make_float4(f0.x, f1.x, f2.x, f3.x);
        float4 hi = make_float4(f0.y, f1.y, f2.y, f3.y);
        if (Cin) {
            float4 c0 = *(const float4*)(Cin + (size_t)row0 * D_ + colb);
            float4 c1 = *(const float4*)(Cin + (size_t)(row0+1) * D_ + colb);
            lo.x += c0.x; lo.y += c0.y; lo.z += c0.z; lo.w += c0.w;
            hi.x += c1.x; hi.y += c1.y; hi.z += c1.z; hi.w += c1.w;
        }
        *(float4*)(Cout + (size_t)row0 * D_ + colb)     = lo;
        *(float4*)(Cout + (size_t)(row0+1) * D_ + colb) = hi;
    }
}

// ---------------- chunk prep: W/intra + forward substitution ----------------
__global__ __launch_bounds__(256) void prep_kernel() {
    __shared__ float wkT[16 * 68];
    __shared__ float rkT[16 * 68];
    __shared__ float Wl[64 * 65];
    __shared__ float gp_s[C_ + 1];

    const int tid = threadIdx.x;
    const int n  = blockIdx.x & (N_ - 1);
    const int bh = blockIdx.x >> 7;
    const int b  = bh >> 2, h = bh & 3;
    const int tx = tid & 15, ty = tid >> 4;

    if (tid <= C_) gp_s[tid] = g_gpow[h][tid];

    ull accW[4][2], accR[4][2];
    #pragma unroll
    for (int a = 0; a < 4; a++) { accW[a][0]=0; accW[a][1]=0; accR[a][0]=0; accR[a][1]=0; }

    // -------- phase 1: W = wk wk^T, R = rk wk^T --------
    for (int ks = 0; ks < 16; ks++) {
        int k0 = ks * 16;
        __syncthreads();
        #pragma unroll
        for (int e = 0; e < 4; e++) {
            int q = tid + e * 256;
            int kk = q & 15, j = q >> 4;
            rkT[kk*68 + j] = g_rk[((size_t)bh*T_ + n*C_ + j) * HD_ + k0 + kk];
            int tw = n*C_ + j - 1;
            wkT[kk*68 + j] = (tw >= 0)
                ? g_rk[((size_t)bh*T_ + tw) * HD_ + k0 + kk] : 0.f;
        }
        __syncthreads();
        #pragma unroll
        for (int kk = 0; kk < 16; kk++) {
            float4 wa = *(const float4*)&wkT[kk*68 + ty*4];
            float4 ra = *(const float4*)&rkT[kk*68 + ty*4];
            ulonglong2 wb = *(const ulonglong2*)&wkT[kk*68 + tx*4];
            ull wa2[4] = {pk2(wa.x,wa.x), pk2(wa.y,wa.y), pk2(wa.z,wa.z), pk2(wa.w,wa.w)};
            ull ra2[4] = {pk2(ra.x,ra.x), pk2(ra.y,ra.y), pk2(ra.z,ra.z), pk2(ra.w,ra.w)};
            #pragma unroll
            for (int a = 0; a < 4; a++) {
                accW[a][0] = fma2(wa2[a], wb.x, accW[a][0]);
                accW[a][1] = fma2(wa2[a], wb.y, accW[a][1]);
                accR[a][0] = fma2(ra2[a], wb.x, accR[a][0]);
                accR[a][1] = fma2(ra2[a], wb.y, accR[a][1]);
            }
        }
    }
    // write masked W*L to smem, masked R*L to global
    size_t ib = ((size_t)(bh * N_ + n)) * C_;
    #pragma unroll
    for (int a = 0; a < 4; a++) {
        int i = ty*4 + a;
        float2 w0 = upk2(accW[a][0]), w1 = upk2(accW[a][1]);
        float2 r0 = upk2(accR[a][0]), r1 = upk2(accR[a][1]);
        float wv[4] = {w0.x, w0.y, w1.x, w1.y};
        float rv[4] = {r0.x, r0.y, r1.x, r1.y};
        #pragma unroll
        for (int q = 0; q < 4; q++) {
            int j = tx*4 + q;
            float lg = (j < i) ? gp_s[i - j] : 0.f;
            Wl[i*65 + j] = wv[q] * lg;
            g_intra[(ib + i) * C_ + j] = rv[q] * lg;
        }
    }
    __syncthreads();

    // -------- phase 2: forward substitution for v and wk (packed f32x2) -------
    const int c = tid;
    ull bvw[C_];
    #pragma unroll
    for (int i = 0; i < C_; i++) {
        float bv = g_v[((size_t)b*T_ + n*C_ + i) * D_ + h*HD_ + c];
        int tw = n*C_ + i - 1;
        float bw = (tw >= 0) ? g_rk[((size_t)bh*T_ + tw) * HD_ + c] : 0.f;
        bvw[i] = pk2(bv, bw);
    }
    #pragma unroll
    for (int i = 1; i < C_; i++) {
        ull acc = 0ULL;
        #pragma unroll
        for (int j = 0; j < C_; j++) {
            if (j < i) {
                float m = Wl[i*65 + j];
                acc = fma2(pk2(m, m), bvw[j], acc);
            }
        }
        bvw[i] = add2(bvw[i], acc ^ SGN2);
    }
    #pragma unroll
    for (int i = 0; i < C_; i++) {
        float2 f = upk2(bvw[i]);
        g_vcorr [(ib + i) * HD_ + c] = f.x;
        g_wkcorr[(ib + i) * HD_ + c] = f.y;
    }
}

// ---------------- chunk scan: 128 independent CTAs (bh x 16-col block) -------
// dyn smem layout (floats):
//   S_s   [256*20]  @ 0
//   wkc   [64*260]  @ 5120
//   rks   [65*260]  @ 21760
//   intr  [64*68]   @ 38660
//   vco   [64*20]   @ 43012
//   vnw   [64*20]   @ 44292      total 45572 floats = 182288 B
#define SCAN_SMEM_BYTES 182288
__global__ __launch_bounds__(256) void scan_kernel() {
    extern __shared__ float sm[];
    float* S_s  = sm;
    float* wkc  = sm + 5120;
    float* rks  = sm + 21760;
    float* intr = sm + 38660;
    float* vco  = sm + 43012;
    float* vnw  = sm + 44292;
    __shared__ float gp_s[C_ + 1];
    __shared__ float s_alpha;

    const int tid = threadIdx.x;
    const int bh  = blockIdx.y;
    const int c0  = blockIdx.x * 16;
    const int b   = bh >> 2, h = bh & 3;

    if (tid <= C_) gp_s[tid] = g_gpow[h][tid];
    if (tid == 0) s_alpha = g_alpha[h];
    for (int q = tid; q < 256 * 20; q += 256) S_s[q] = 0.f;
    __syncthreads();

    const int iA = tid >> 2;            // 0..63 (row within chunk)
    const int cq = (tid & 3) << 2;      // 0,4,8,12 (col group)

    for (int n = 0; n < N_; n++) {
        size_t cb = ((size_t)(bh * N_ + n)) * C_;
        // ---- tile loads ----
        #pragma unroll
        for (int rr = 0; rr < 16; rr++) {
            int q = tid + (rr << 8);
            int i = q >> 6, k4 = (q & 63) << 2;
            *(float4*)&wkc[i*260 + k4] = *(const float4*)(g_wkcorr + (cb + i)*HD_ + k4);
        }
        #pragma unroll
        for (int rr = 0; rr < 17; rr++) {
            int q = tid + (rr << 8);
            if (q < 4160) {
                int i = q >> 6, k4 = (q & 63) << 2;
                int t = n*C_ - 1 + i;
                float4 v = (t >= 0) ? *(const float4*)(g_rk + ((size_t)bh*T_ + t)*HD_ + k4)
                                    : make_float4(0.f, 0.f, 0.f, 0.f);
                *(float4*)&rks[i*260 + k4] = v;
            }
        }
        #pragma unroll
        for (int rr = 0; rr < 4; rr++) {
            int q = tid + (rr << 8);
            int i = q >> 4, j4 = (q & 15) << 2;
            *(float4*)&intr[i*68 + j4] = *(const float4*)(g_intra + (cb + i)*C_ + j4);
        }
        {
            int i = tid >> 2;
            *(float4*)&vco[i*20 + cq] = *(const float4*)(g_vcorr + (cb + i)*HD_ + c0 + cq);
        }
        __syncthreads();

        // ---- (A) t1 = wkc @ S, orr = rk @ S ; v_new = vco - t1 ----
        ull t1a = 0, t1b = 0, oa = 0, ob = 0;
        {
            const float* wrow = wkc + iA*260;
            const float* rrow = rks + (iA + 1)*260;
            #pragma unroll 4
            for (int k = 0; k < HD_; k += 4) {
                float4 w4 = *(const float4*)(wrow + k);
                float4 r4 = *(const float4*)(rrow + k);
                float wl[4] = {w4.x, w4.y, w4.z, w4.w};
                float rl[4] = {r4.x, r4.y, r4.z, r4.w};
                #pragma unroll
                for (int u = 0; u < 4; u++) {
                    ulonglong2 s = *(const ulonglong2*)&S_s[(k + u)*20 + cq];
                    ull w2 = pk2(wl[u], wl[u]);
                    ull r2 = pk2(rl[u], rl[u]);
                    t1a = fma2(w2, s.x, t1a);
                    t1b = fma2(w2, s.y, t1b);
                    oa  = fma2(r2, s.x, oa);
                    ob  = fma2(r2, s.y, ob);
                }
            }
            ulonglong2 vc2 = *(const ulonglong2*)&vco[iA*20 + cq];
            ulonglong2 vn2;
            vn2.x = add2(vc2.x, t1a ^ SGN2);
            vn2.y = add2(vc2.y, t1b ^ SGN2);
            *(ulonglong2*)&vnw[iA*20 + cq] = vn2;
        }
        __syncthreads();

        // ---- (C) o = gamma^i * orr + intra @ v_new ; write alpha*o ----
        {
            float gi = gp_s[iA];
            ull gi2 = pk2(gi, gi);
            oa = mul2(oa, gi2); ob = mul2(ob, gi2);
            const float* irow = intr + iA*68;
            #pragma unroll 8
            for (int j = 0; j < C_; j++) {
                float m = irow[j];
                ull m2 = pk2(m, m);
                ulonglong2 vn = *(const ulonglong2*)&vnw[j*20 + cq];
                oa = fma2(m2, vn.x, oa);
                ob = fma2(m2, vn.y, ob);
            }
            ull al2 = pk2(s_alpha, s_alpha);
            oa = mul2(oa, al2); ob = mul2(ob, al2);
            float2 p0 = upk2(oa), p1 = upk2(ob);
            *(float4*)(g_o + ((size_t)b*T_ + n*C_ + iA)*D_ + h*HD_ + c0 + cq)
                = make_float4(p0.x, p0.y, p1.x, p1.y);
        }
        __syncthreads();

        // ---- (D) S = gamma^C * S + wk_g^T @ v_new ----
        {
            float gC = gp_s[C_];
            ull gc2 = pk2(gC, gC);
            ull s8[8];
            #pragma unroll
            for (int q = 0; q < 4; q++) {
                ulonglong2 t = *(const ulonglong2*)&S_s[tid*20 + q*4];
                s8[2*q]   = mul2(t.x, gc2);
                s8[2*q+1] = mul2(t.y, gc2);
            }
            #pragma unroll 4
            for (int j = 0; j < C_; j++) {
                float w = rks[j*260 + tid] * gp_s[63 - j];
                ull w2 = pk2(w, w);
                #pragma unroll
                for (int q = 0; q < 4; q++) {
                    ulonglong2 vn = *(const ulonglong2*)&vnw[j*20 + q*4];
                    s8[2*q]   = fma2(w2, vn.x, s8[2*q]);
                    s8[2*q+1] = fma2(w2, vn.y, s8[2*q+1]);
                }
            }
            #pragma unroll
            for (int q = 0; q < 4; q++) {
                ulonglong2 t;
                t.x = s8[2*q]; t.y = s8[2*q+1];
                *(ulonglong2*)&S_s[tid*20 + q*4] = t;
            }
        }
        __syncthreads();
    }
}

// ---------------- launch ----------------
extern "C" void kernel_launch(void* const* d_in, const int* in_sizes, int n_in,
                              void* d_out, int out_size) {
    const float* x     = (const float*)d_in[0];
    const float* Ww    = (const float*)d_in[1];
    const float* Wr    = (const float*)d_in[2];
    const float* decay = (const float*)d_in[3];
    const float* lalp  = (const float*)d_in[4];
    float* out = (float*)d_out;

    cudaFuncSetAttribute(scan_kernel, cudaFuncAttributeMaxDynamicSharedMemorySize,
                         SCAN_SMEM_BYTES);

    void *pv = nullptr, *po = nullptr;
    cudaGetSymbolAddress(&pv, g_v);
    cudaGetSymbolAddress(&po, g_o);

    setup_kernel<<<1, 32>>>(decay, lalp);
    rk_kernel<<<(B_ * T_ * H_) / 8, 256>>>(x);
    sgemm_tn<<<dim3(D_ / 128, (B_ * T_) / 128), 256>>>(x, Ww, nullptr, (float*)pv);
    prep_kernel<<<BH_ * N_, 256>>>();
    scan_kernel<<<dim3(16, BH_), 256, SCAN_SMEM_BYTES>>>();
    sgemm_tn<<<dim3(D_ / 128, (B_ * T_) / 128), 256>>>((const float*)po, Wr, x, out);
}

// round 4
// speedup vs baseline: 1.4030x; 1.4030x over previous
#include <cuda_runtime.h>
#include <cuda_bf16.h>

// ---------------- problem constants ----------------
#define B_    2
#define T_    8192
#define D_    1024
#define H_    4
#define HD_   256
#define C_    64
#define N_    128
#define BH_   8

typedef unsigned long long ull;

// ---------------- f32x2 helpers (PTX-only on sm_103a) ----------------
__device__ __forceinline__ ull pk2(float a, float b) {
    ull r; asm("mov.b64 %0, {%1, %2};" : "=l"(r) : "f"(a), "f"(b)); return r;
}
__device__ __forceinline__ float2 upk2(ull v) {
    float2 f; asm("mov.b64 {%0, %1}, %2;" : "=f"(f.x), "=f"(f.y) : "l"(v)); return f;
}
__device__ __forceinline__ ull fma2(ull a, ull b, ull c) {
    ull d; asm("fma.rn.f32x2 %0, %1, %2, %3;" : "=l"(d) : "l"(a), "l"(b), "l"(c)); return d;
}
__device__ __forceinline__ ull add2(ull a, ull b) {
    ull d; asm("add.rn.f32x2 %0, %1, %2;" : "=l"(d) : "l"(a), "l"(b)); return d;
}
__device__ __forceinline__ ull mul2(ull a, ull b) {
    ull d; asm("mul.rn.f32x2 %0, %1, %2;" : "=l"(d) : "l"(a), "l"(b)); return d;
}
#define SGN2 0x8000000080000000ULL

__device__ __forceinline__ unsigned smem_u32(const void* p) {
    unsigned a;
    asm("{ .reg .u64 t; cvta.to.shared.u64 t, %1; cvt.u32.u64 %0, t; }" : "=r"(a) : "l"(p));
    return a;
}

// ---------------- device scratch (no allocation allowed) ----------------
__device__ float g_v[(size_t)B_ * T_ * D_];            // x @ Ww^T, (b*T+t, D) layout
__device__ float g_rk[(size_t)BH_ * T_ * HD_];         // normalized keys, (bh, t, d)
__device__ float g_vcorr[(size_t)BH_ * N_ * C_ * HD_]; // A @ v
__device__ float g_wkcorr[(size_t)BH_ * N_ * C_ * HD_];// A @ wk
__device__ float g_intra[(size_t)BH_ * N_ * C_ * C_];  // strict(rk wk^T * L)
__device__ float g_o[(size_t)B_ * T_ * D_];            // alpha * o, (b*T+t, D)
__device__ float g_gpow[H_][C_ + 1];                   // gamma^0..gamma^64
__device__ float g_alpha[H_];

// bf16 copies for tensor-core GEMMs
__device__ __nv_bfloat16 g_xb [(size_t)B_ * T_ * D_];
__device__ __nv_bfloat16 g_ob [(size_t)B_ * T_ * D_];
__device__ __nv_bfloat16 g_Wwb[(size_t)D_ * D_];
__device__ __nv_bfloat16 g_Wrb[(size_t)D_ * D_];

// ---------------- setup ----------------
__global__ void setup_kernel(const float* __restrict__ decay,
                             const float* __restrict__ log_alpha) {
    int h = threadIdx.x;
    if (h < H_) {
        float g = 1.f / (1.f + expf(-decay[h]));
        g_alpha[h] = expf(log_alpha[h]);
        float p = 1.f;
        for (int i = 0; i <= C_; i++) { g_gpow[h][i] = p; p *= g; }
    }
}

// ---------------- f32 -> bf16 conversion (8 elems/thread) ----------------
__global__ __launch_bounds__(256) void conv_bf16(const float* __restrict__ in,
                                                 __nv_bfloat16* __restrict__ out) {
    size_t i = ((size_t)blockIdx.x * 256 + threadIdx.x) * 8;
    float4 a = *(const float4*)(in + i);
    float4 b = *(const float4*)(in + i + 4);
    __nv_bfloat162 r0 = __floats2bfloat162_rn(a.x, a.y);
    __nv_bfloat162 r1 = __floats2bfloat162_rn(a.z, a.w);
    __nv_bfloat162 r2 = __floats2bfloat162_rn(b.x, b.y);
    __nv_bfloat162 r3 = __floats2bfloat162_rn(b.z, b.w);
    uint4 pk;
    pk.x = *(unsigned*)&r0; pk.y = *(unsigned*)&r1;
    pk.z = *(unsigned*)&r2; pk.w = *(unsigned*)&r3;
    *(uint4*)(out + i) = pk;
}

// ---------------- rk: normalize per head, store (bh,t,d) ----------------
__global__ __launch_bounds__(256) void rk_kernel(const float* __restrict__ x) {
    int warp = threadIdx.x >> 5, lane = threadIdx.x & 31;
    int row = blockIdx.x * 8 + warp;            // (b*T+t)*H + h, total 65536
    int h  = row & (H_ - 1);
    int bt = row >> 2;
    const float* xp = x + (size_t)bt * D_ + h * HD_ + lane * 8;
    float4 v0 = *(const float4*)(xp);
    float4 v1 = *(const float4*)(xp + 4);
    float ss = v0.x*v0.x + v0.y*v0.y + v0.z*v0.z + v0.w*v0.w
             + v1.x*v1.x + v1.y*v1.y + v1.z*v1.z + v1.w*v1.w;
    #pragma unroll
    for (int o = 16; o; o >>= 1) ss += __shfl_xor_sync(0xffffffffu, ss, o);
    float inv = 1.f / fmaxf(sqrtf(ss), 1e-12f);
    int b = bt >> 13, t = bt & (T_ - 1);
    float* rp = g_rk + ((size_t)(b * H_ + h) * T_ + t) * HD_ + lane * 8;
    *(float4*)(rp)     = make_float4(v0.x*inv, v0.y*inv, v0.z*inv, v0.w*inv);
    *(float4*)(rp + 4) = make_float4(v1.x*inv, v1.y*inv, v1.z*inv, v1.w*inv);
}

// ---------------- bf16 tensor-core GEMM (TN): C = (Cin?Cin:0) + A @ W^T -------
// M=16384, N=1024, K=1024. CTA 128x128, 256 thr, warp 32x64, K-stage 32.
#define RSE 40   // smem row stride in bf16 elements (80 bytes; conflict-free ldmatrix)
__global__ __launch_bounds__(256) void gemm_bf16_tn(const __nv_bfloat16* __restrict__ A,
                                                    const __nv_bfloat16* __restrict__ W,
                                                    const float* __restrict__ Cin,
                                                    float* __restrict__ Cout) {
    __shared__ __nv_bfloat16 As[128 * RSE];
    __shared__ __nv_bfloat16 Bs[128 * RSE];
    const int tid = threadIdx.x;
    const int bm = blockIdx.y * 128, bn = blockIdx.x * 128;
    const int wid = tid >> 5, lane = tid & 31;
    const int wm = (wid & 3) * 32, wn = (wid >> 2) * 64;

    // gmem staging: each thread loads 2x 16B (rows r, r+64; k-offset (tid&3)*8)
    const int lr = tid >> 2, lk = (tid & 3) * 8;
    const __nv_bfloat16* Ap0 = A + (size_t)(bm + lr) * D_ + lk;
    const __nv_bfloat16* Ap1 = A + (size_t)(bm + lr + 64) * D_ + lk;
    const __nv_bfloat16* Wp0 = W + (size_t)(bn + lr) * D_ + lk;
    const __nv_bfloat16* Wp1 = W + (size_t)(bn + lr + 64) * D_ + lk;

    // ldmatrix lane address templates (bytes)
    const unsigned a_base = smem_u32(As) +
        (unsigned)((wm + (lane & 7) + ((lane >> 3) & 1) * 8) * (RSE * 2) + (lane >> 4) * 16);
    const unsigned b_base = smem_u32(Bs) +
        (unsigned)((wn + (lane & 7) + ((lane >> 4) & 1) * 8) * (RSE * 2) + ((lane >> 3) & 1) * 16);

    float acc[2][8][4];
    #pragma unroll
    for (int mt = 0; mt < 2; mt++)
        #pragma unroll
        for (int nt = 0; nt < 8; nt++)
            #pragma unroll
            for (int q = 0; q < 4; q++) acc[mt][nt][q] = 0.f;

    uint4 pa0 = *(const uint4*)(Ap0), pa1 = *(const uint4*)(Ap1);
    uint4 pb0 = *(const uint4*)(Wp0), pb1 = *(const uint4*)(Wp1);

    for (int k0 = 0; k0 < D_; k0 += 32) {
        __syncthreads();
        *(uint4*)&As[lr * RSE + lk]        = pa0;
        *(uint4*)&As[(lr + 64) * RSE + lk] = pa1;
        *(uint4*)&Bs[lr * RSE + lk]        = pb0;
        *(uint4*)&Bs[(lr + 64) * RSE + lk] = pb1;
        __syncthreads();
        if (k0 + 32 < D_) {
            pa0 = *(const uint4*)(Ap0 + k0 + 32);
            pa1 = *(const uint4*)(Ap1 + k0 + 32);
            pb0 = *(const uint4*)(Wp0 + k0 + 32);
            pb1 = *(const uint4*)(Wp1 + k0 + 32);
        }
        #pragma unroll
        for (int kk = 0; kk < 2; kk++) {
            unsigned ka = a_base + kk * 32;
            unsigned kb = b_base + kk * 32;
            unsigned af[2][4], bf[4][4];
            #pragma unroll
            for (int mt = 0; mt < 2; mt++) {
                unsigned ad = ka + mt * 16 * (RSE * 2);
                asm volatile("ldmatrix.sync.aligned.m8n8.x4.shared.b16 {%0,%1,%2,%3}, [%4];"
                    : "=r"(af[mt][0]), "=r"(af[mt][1]), "=r"(af[mt][2]), "=r"(af[mt][3])
                    : "r"(ad));
            }
            #pragma unroll
            for (int j = 0; j < 4; j++) {
                unsigned bd = kb + j * 16 * (RSE * 2);
                asm volatile("ldmatrix.sync.aligned.m8n8.x4.shared.b16 {%0,%1,%2,%3}, [%4];"
                    : "=r"(bf[j][0]), "=r"(bf[j][1]), "=r"(bf[j][2]), "=r"(bf[j][3])
                    : "r"(bd));
            }
            #pragma unroll
            for (int mt = 0; mt < 2; mt++)
                #pragma unroll
                for (int nt = 0; nt < 8; nt++) {
                    unsigned b0 = bf[nt >> 1][(nt & 1) * 2 + 0];
                    unsigned b1 = bf[nt >> 1][(nt & 1) * 2 + 1];
                    asm volatile(
                        "mma.sync.aligned.m16n8k16.row.col.f32.bf16.bf16.f32 "
                        "{%0,%1,%2,%3}, {%4,%5,%6,%7}, {%8,%9}, {%0,%1,%2,%3};"
                        : "+f"(acc[mt][nt][0]), "+f"(acc[mt][nt][1]),
                          "+f"(acc[mt][nt][2]), "+f"(acc[mt][nt][3])
                        : "r"(af[mt][0]), "r"(af[mt][1]), "r"(af[mt][2]), "r"(af[mt][3]),
                          "r"(b0), "r"(b1));
                }
        }
    }

    // epilogue
    const int rr = lane >> 2, cc = (lane & 3) * 2;
    #pragma unroll
    for (int mt = 0; mt < 2; mt++) {
        int row = bm + wm + mt * 16 + rr;
        #pragma unroll
        for (int nt = 0; nt < 8; nt++) {
            int col = bn + wn + nt * 8 + cc;
            float2 lo = make_float2(acc[mt][nt][0], acc[mt][nt][1]);
            float2 hi = make_float2(acc[mt][nt][2], acc[mt][nt][3]);
            if (Cin) {
                float2 c0 = *(const float2*)(Cin + (size_t)row * D_ + col);
                float2 c1 = *(const float2*)(Cin + (size_t)(row + 8) * D_ + col);
                lo.x += c0.x; lo.y += c0.y; hi.x += c1.x; hi.y += c1.y;
            }
            *(float2*)(Cout + (size_t)row * D_ + col)       = lo;
            *(float2*)(Cout + (size_t)(row + 8) * D_ + col) = hi;
        }
    }
}

// ---------------- chunk prep: W/intra + forward substitution ----------------
__global__ __launch_bounds__(256) void prep_kernel() {
    __shared__ float wkT[16 * 68];
    __shared__ float rkT[16 * 68];
    __shared__ float Wl[64 * 65];
    __shared__ float gp_s[C_ + 1];

    const int tid = threadIdx.x;
    const int n  = blockIdx.x & (N_ - 1);
    const int bh = blockIdx.x >> 7;
    const int b  = bh >> 2, h = bh & 3;
    const int tx = tid & 15, ty = tid >> 4;

    if (tid <= C_) gp_s[tid] = g_gpow[h][tid];

    ull accW[4][2], accR[4][2];
    #pragma unroll
    for (int a = 0; a < 4; a++) { accW[a][0]=0; accW[a][1]=0; accR[a][0]=0; accR[a][1]=0; }

    // -------- phase 1: W = wk wk^T, R = rk wk^T --------
    for (int ks = 0; ks < 16; ks++) {
        int k0 = ks * 16;
        __syncthreads();
        #pragma unroll
        for (int e = 0; e < 4; e++) {
            int q = tid + e * 256;
            int kk = q & 15, j = q >> 4;
            rkT[kk*68 + j] = g_rk[((size_t)bh*T_ + n*C_ + j) * HD_ + k0 + kk];
            int tw = n*C_ + j - 1;
            wkT[kk*68 + j] = (tw >= 0)
                ? g_rk[((size_t)bh*T_ + tw) * HD_ + k0 + kk] : 0.f;
        }
        __syncthreads();
        #pragma unroll
        for (int kk = 0; kk < 16; kk++) {
            float4 wa = *(const float4*)&wkT[kk*68 + ty*4];
            float4 ra = *(const float4*)&rkT[kk*68 + ty*4];
            ulonglong2 wb = *(const ulonglong2*)&wkT[kk*68 + tx*4];
            ull wa2[4] = {pk2(wa.x,wa.x), pk2(wa.y,wa.y), pk2(wa.z,wa.z), pk2(wa.w,wa.w)};
            ull ra2[4] = {pk2(ra.x,ra.x), pk2(ra.y,ra.y), pk2(ra.z,ra.z), pk2(ra.w,ra.w)};
            #pragma unroll
            for (int a = 0; a < 4; a++) {
                accW[a][0] = fma2(wa2[a], wb.x, accW[a][0]);
                accW[a][1] = fma2(wa2[a], wb.y, accW[a][1]);
                accR[a][0] = fma2(ra2[a], wb.x, accR[a][0]);
                accR[a][1] = fma2(ra2[a], wb.y, accR[a][1]);
            }
        }
    }
    // write masked W*L to smem, masked R*L to global
    size_t ib = ((size_t)(bh * N_ + n)) * C_;
    #pragma unroll
    for (int a = 0; a < 4; a++) {
        int i = ty*4 + a;
        float2 w0 = upk2(accW[a][0]), w1 = upk2(accW[a][1]);
        float2 r0 = upk2(accR[a][0]), r1 = upk2(accR[a][1]);
        float wv[4] = {w0.x, w0.y, w1.x, w1.y};
        float rv[4] = {r0.x, r0.y, r1.x, r1.y};
        #pragma unroll
        for (int q = 0; q < 4; q++) {
            int j = tx*4 + q;
            float lg = (j < i) ? gp_s[i - j] : 0.f;
            Wl[i*65 + j] = wv[q] * lg;
            g_intra[(ib + i) * C_ + j] = rv[q] * lg;
        }
    }
    __syncthreads();

    // -------- phase 2: forward substitution for v and wk (packed f32x2) -------
    const int c = tid;
    ull bvw[C_];
    #pragma unroll
    for (int i = 0; i < C_; i++) {
        float bv = g_v[((size_t)b*T_ + n*C_ + i) * D_ + h*HD_ + c];
        int tw = n*C_ + i - 1;
        float bw = (tw >= 0) ? g_rk[((size_t)bh*T_ + tw) * HD_ + c] : 0.f;
        bvw[i] = pk2(bv, bw);
    }
    #pragma unroll
    for (int i = 1; i < C_; i++) {
        ull acc = 0ULL;
        #pragma unroll
        for (int j = 0; j < C_; j++) {
            if (j < i) {
                float m = Wl[i*65 + j];
                acc = fma2(pk2(m, m), bvw[j], acc);
            }
        }
        bvw[i] = add2(bvw[i], acc ^ SGN2);
    }
    #pragma unroll
    for (int i = 0; i < C_; i++) {
        float2 f = upk2(bvw[i]);
        g_vcorr [(ib + i) * HD_ + c] = f.x;
        g_wkcorr[(ib + i) * HD_ + c] = f.y;
    }
}

// ---------------- chunk scan: 128 independent CTAs (bh x 16-col block) -------
#define SCAN_SMEM_BYTES 182288
__global__ __launch_bounds__(256) void scan_kernel() {
    extern __shared__ float sm[];
    float* S_s  = sm;
    float* wkc  = sm + 5120;
    float* rks  = sm + 21760;
    float* intr = sm + 38660;
    float* vco  = sm + 43012;
    float* vnw  = sm + 44292;
    __shared__ float gp_s[C_ + 1];
    __shared__ float s_alpha;

    const int tid = threadIdx.x;
    const int bh  = blockIdx.y;
    const int c0  = blockIdx.x * 16;
    const int b   = bh >> 2, h = bh & 3;

    if (tid <= C_) gp_s[tid] = g_gpow[h][tid];
    if (tid == 0) s_alpha = g_alpha[h];
    for (int q = tid; q < 256 * 20; q += 256) S_s[q] = 0.f;
    __syncthreads();

    const int iA = tid >> 2;            // 0..63 (row within chunk)
    const int cq = (tid & 3) << 2;      // 0,4,8,12 (col group)

    for (int n = 0; n < N_; n++) {
        size_t cb = ((size_t)(bh * N_ + n)) * C_;
        #pragma unroll
        for (int rr = 0; rr < 16; rr++) {
            int q = tid + (rr << 8);
            int i = q >> 6, k4 = (q & 63) << 2;
            *(float4*)&wkc[i*260 + k4] = *(const float4*)(g_wkcorr + (cb + i)*HD_ + k4);
        }
        #pragma unroll
        for (int rr = 0; rr < 17; rr++) {
            int q = tid + (rr << 8);
            if (q < 4160) {
                int i = q >> 6, k4 = (q & 63) << 2;
                int t = n*C_ - 1 + i;
                float4 v = (t >= 0) ? *(const float4*)(g_rk + ((size_t)bh*T_ + t)*HD_ + k4)
                                    : make_float4(0.f, 0.f, 0.f, 0.f);
                *(float4*)&rks[i*260 + k4] = v;
            }
        }
        #pragma unroll
        for (int rr = 0; rr < 4; rr++) {
            int q = tid + (rr << 8);
            int i = q >> 4, j4 = (q & 15) << 2;
            *(float4*)&intr[i*68 + j4] = *(const float4*)(g_intra + (cb + i)*C_ + j4);
        }
        {
            int i = tid >> 2;
            *(float4*)&vco[i*20 + cq] = *(const float4*)(g_vcorr + (cb + i)*HD_ + c0 + cq);
        }
        __syncthreads();

        // ---- (A) t1 = wkc @ S, orr = rk @ S ; v_new = vco - t1 ----
        ull t1a = 0, t1b = 0, oa = 0, ob = 0;
        {
            const float* wrow = wkc + iA*260;
            const float* rrow = rks + (iA + 1)*260;
            #pragma unroll 4
            for (int k = 0; k < HD_; k += 4) {
                float4 w4 = *(const float4*)(wrow + k);
                float4 r4 = *(const float4*)(rrow + k);
                float wl[4] = {w4.x, w4.y, w4.z, w4.w};
                float rl[4] = {r4.x, r4.y, r4.z, r4.w};
                #pragma unroll
                for (int u = 0; u < 4; u++) {
                    ulonglong2 s = *(const ulonglong2*)&S_s[(k + u)*20 + cq];
                    ull w2 = pk2(wl[u], wl[u]);
                    ull r2 = pk2(rl[u], rl[u]);
                    t1a = fma2(w2, s.x, t1a);
                    t1b = fma2(w2, s.y, t1b);
                    oa  = fma2(r2, s.x, oa);
                    ob  = fma2(r2, s.y, ob);
                }
            }
            ulonglong2 vc2 = *(const ulonglong2*)&vco[iA*20 + cq];
            ulonglong2 vn2;
            vn2.x = add2(vc2.x, t1a ^ SGN2);
            vn2.y = add2(vc2.y, t1b ^ SGN2);
            *(ulonglong2*)&vnw[iA*20 + cq] = vn2;
        }
        __syncthreads();

        // ---- (C) o = gamma^i * orr + intra @ v_new ; write alpha*o ----
        {
            float gi = gp_s[iA];
            ull gi2 = pk2(gi, gi);
            oa = mul2(oa, gi2); ob = mul2(ob, gi2);
            const float* irow = intr + iA*68;
            #pragma unroll 8
            for (int j = 0; j < C_; j++) {
                float m = irow[j];
                ull m2 = pk2(m, m);
                ulonglong2 vn = *(const ulonglong2*)&vnw[j*20 + cq];
                oa = fma2(m2, vn.x, oa);
                ob = fma2(m2, vn.y, ob);
            }
            ull al2 = pk2(s_alpha, s_alpha);
            oa = mul2(oa, al2); ob = mul2(ob, al2);
            float2 p0 = upk2(oa), p1 = upk2(ob);
            *(float4*)(g_o + ((size_t)b*T_ + n*C_ + iA)*D_ + h*HD_ + c0 + cq)
                = make_float4(p0.x, p0.y, p1.x, p1.y);
        }
        __syncthreads();

        // ---- (D) S = gamma^C * S + wk_g^T @ v_new ----
        {
            float gC = gp_s[C_];
            ull gc2 = pk2(gC, gC);
            ull s8[8];
            #pragma unroll
            for (int q = 0; q < 4; q++) {
                ulonglong2 t = *(const ulonglong2*)&S_s[tid*20 + q*4];
                s8[2*q]   = mul2(t.x, gc2);
                s8[2*q+1] = mul2(t.y, gc2);
            }
            #pragma unroll 4
            for (int j = 0; j < C_; j++) {
                float w = rks[j*260 + tid] * gp_s[63 - j];
                ull w2 = pk2(w, w);
                #pragma unroll
                for (int q = 0; q < 4; q++) {
                    ulonglong2 vn = *(const ulonglong2*)&vnw[j*20 + q*4];
                    s8[2*q]   = fma2(w2, vn.x, s8[2*q]);
                    s8[2*q+1] = fma2(w2, vn.y, s8[2*q+1]);
                }
            }
            #pragma unroll
            for (int q = 0; q < 4; q++) {
                ulonglong2 t;
                t.x = s8[2*q]; t.y = s8[2*q+1];
                *(ulonglong2*)&S_s[tid*20 + q*4] = t;
            }
        }
        __syncthreads();
    }
}

// ---------------- launch ----------------
extern "C" void kernel_launch(void* const* d_in, const int* in_sizes, int n_in,
                              void* d_out, int out_size) {
    const float* x     = (const float*)d_in[0];
    const float* Ww    = (const float*)d_in[1];
    const float* Wr    = (const float*)d_in[2];
    const float* decay = (const float*)d_in[3];
    const float* lalp  = (const float*)d_in[4];
    float* out = (float*)d_out;

    cudaFuncSetAttribute(scan_kernel, cudaFuncAttributeMaxDynamicSharedMemorySize,
                         SCAN_SMEM_BYTES);

    void *pv = nullptr, *po = nullptr, *pxb = nullptr, *pob = nullptr;
    void *pwwb = nullptr, *pwrb = nullptr;
    cudaGetSymbolAddress(&pv, g_v);
    cudaGetSymbolAddress(&po, g_o);
    cudaGetSymbolAddress(&pxb, g_xb);
    cudaGetSymbolAddress(&pob, g_ob);
    cudaGetSymbolAddress(&pwwb, g_Wwb);
    cudaGetSymbolAddress(&pwrb, g_Wrb);

    const size_t ND = (size_t)B_ * T_ * D_;   // 16,777,216
    const size_t NW = (size_t)D_ * D_;        // 1,048,576

    setup_kernel<<<1, 32>>>(decay, lalp);
    rk_kernel<<<(B_ * T_ * H_) / 8, 256>>>(x);
    conv_bf16<<<(int)(ND / 2048), 256>>>(x,  (__nv_bfloat16*)pxb);
    conv_bf16<<<(int)(NW / 2048), 256>>>(Ww, (__nv_bfloat16*)pwwb);
    conv_bf16<<<(int)(NW / 2048), 256>>>(Wr, (__nv_bfloat16*)pwrb);
    gemm_bf16_tn<<<dim3(D_ / 128, (B_ * T_) / 128), 256>>>(
        (const __nv_bfloat16*)pxb, (const __nv_bfloat16*)pwwb, nullptr, (float*)pv);
    prep_kernel<<<BH_ * N_, 256>>>();
    scan_kernel<<<dim3(16, BH_), 256, SCAN_SMEM_BYTES>>>();
    conv_bf16<<<(int)(ND / 2048), 256>>>((const float*)po, (__nv_bfloat16*)pob);
    gemm_bf16_tn<<<dim3(D_ / 128, (B_ * T_) / 128), 256>>>(
        (const __nv_bfloat16*)pob, (const __nv_bfloat16*)pwrb, x, out);
}